// round 3
// baseline (speedup 1.0000x reference)
#include <cuda_runtime.h>
#include <stdint.h>

#define THREADS 128
#define ROWS    128      // rows per block
#define PCOUNT  64       // predicates
#define PAD     129      // conflict-free row stride in shared
#define C_MAX   128
#define NLIT    (C_MAX*3)
#define EROWS   128      // E-table: exp(+g_p) at row p, exp(-g_p) at row p+64

// CSR over predicates, built once per launch by prep_kernel.
// g_ent[k] = {e_self | e_other1<<16, e_other2, float_bits(sign*w), 0}
//   (E-row offsets pre-multiplied by PAD; sign folded into both the E-row
//    choice (+g vs -g half) and the weight.)
__device__ uint4 g_ent[NLIT];
__device__ int   g_start[PCOUNT + 1];

__device__ __forceinline__ float frcp(float x){ float y; asm("rcp.approx.f32 %0, %1;" : "=f"(y) : "f"(x)); return y; }
__device__ __forceinline__ float fex2(float x){ float y; asm("ex2.approx.f32 %0, %1;" : "=f"(y) : "f"(x)); return y; }

// literal_idx may physically be int32 (JAX x64-disabled) or int64; detect:
// int64 view of int32 data fuses two random indices -> out of [0,64) w.h.p.
__global__ void prep_kernel(const float* __restrict__ cw,
                            const void* __restrict__ litraw,
                            const int* __restrict__ sgn, int C)
{
    __shared__ int pidx[NLIT];          // predicate per literal slot
    __shared__ int st[PCOUNT + 1];
    __shared__ int sh_is64;
    const int tid = threadIdx.x;
    const int nl = C * 3;

    if (tid == 0){
        const long long* v64 = (const long long*)litraw;
        int ok = 1;
        for (int k = 0; k < nl/2; k++){            // stays in int32-buffer bounds
            long long v = v64[k];
            if (v < 0 || v >= PCOUNT){ ok = 0; break; }
        }
        sh_is64 = ok;
    }
    __syncthreads();
    const int is64 = sh_is64;

    for (int i = tid; i < nl; i += blockDim.x)
        pidx[i] = is64 ? (int)((const long long*)litraw)[i]
                       :       ((const int*)litraw)[i];
    __syncthreads();

    // counts -> serial prefix (tiny, deterministic)
    int cnt = 0;
    if (tid < PCOUNT){
        for (int i = 0; i < nl; i++) cnt += (pidx[i] == tid);
    }
    if (tid < PCOUNT) st[tid + 1] = cnt;
    __syncthreads();
    if (tid == 0){
        st[0] = 0;
        for (int p = 0; p < PCOUNT; p++) st[p + 1] += st[p];
        for (int p = 0; p <= PCOUNT; p++) g_start[p] = st[p];
    }
    __syncthreads();

    // one thread per predicate writes its entries in literal order (deterministic)
    if (tid < PCOUNT){
        int o = st[tid];
        for (int i = 0; i < nl; i++){
            if (pidx[i] != tid) continue;
            int c = i / 3, l = i - c*3;
            float w = fminf(fmaxf(cw[c], 0.0f), 500.0f);
            unsigned e[3];
            #pragma unroll
            for (int j = 0; j < 3; j++){
                int pj  = pidx[c*3 + j];
                int sbj = sgn[c*3 + j];                       // 1 -> +g, 0 -> -g
                e[j] = (unsigned)((pj + (sbj ? 0 : PCOUNT)) * PAD);
            }
            int o1 = (l == 0) ? 1 : 0;
            int o2 = (l == 2) ? 1 : 2;
            float ws = sgn[i] ? w : -w;
            g_ent[o++] = make_uint4(e[l] | (e[o1] << 16), e[o2],
                                    __float_as_uint(ws), 0u);
        }
    }
}

__global__ void __launch_bounds__(THREADS)
main_kernel(const float* __restrict__ ga, float* __restrict__ out, int B)
{
    extern __shared__ float sh[];
    float* __restrict__ E = sh;                         // EROWS*PAD
    float* __restrict__ A = sh + EROWS*PAD;             // PCOUNT*PAD (write-once)
    uint4* ENT = (uint4*)(sh + EROWS*PAD + PCOUNT*PAD); // NLIT entries
    int*   ST  = (int*)(ENT + NLIT);                    // PCOUNT+1

    const int tid = threadIdx.x;
    const long long rowbase = (long long)blockIdx.x * ROWS;
    long long rem = (long long)B - rowbase;
    const int nrows = rem < ROWS ? (int)rem : ROWS;
    const size_t base = (size_t)rowbase * PCOUNT;

    for (int i = tid; i < NLIT; i += THREADS) ENT[i] = g_ent[i];
    if (tid <= PCOUNT) ST[tid] = g_start[tid];

    // Phase A: coalesced tile load; build exp table (exp(+g) and its rcp).
    const float4* ga4 = (const float4*)(ga + base);
    const float L2E = 1.4426950408889634f;
    for (int i = tid; i < ROWS*PCOUNT/4; i += THREADS){
        int o = i * 4, row = o >> 6, p = o & (PCOUNT-1);
        if (row < nrows){
            float4 g = ga4[i];
            float t;
            t = fex2(g.x*L2E); E[(p  )*PAD+row] = t; E[(p+PCOUNT  )*PAD+row] = frcp(t);
            t = fex2(g.y*L2E); E[(p+1)*PAD+row] = t; E[(p+PCOUNT+1)*PAD+row] = frcp(t);
            t = fex2(g.z*L2E); E[(p+2)*PAD+row] = t; E[(p+PCOUNT+2)*PAD+row] = frcp(t);
            t = fex2(g.w*L2E); E[(p+3)*PAD+row] = t; E[(p+PCOUNT+3)*PAD+row] = frcp(t);
        }
    }
    __syncthreads();

    // Phase B (transposed): per predicate, gather contributions into a REGISTER
    // accumulator (no smem RMW chain), write A[p] once. Entry loads are warp
    // broadcasts; E-gathers are conflict-free (lane stride = PAD floats).
    #pragma unroll 1
    for (int p = 0; p < PCOUNT; p++){
        int s = ST[p], e = ST[p+1];
        float acc = 0.0f;
        for (int k = s; k < e; k++){
            uint4 en = ENT[k];
            float x = E[(en.x & 0xFFFF) + tid];     // self literal
            float y = E[(en.x >> 16)    + tid];     // other literal 1
            float z = E[en.y            + tid];     // other literal 2
            acc = fmaf(__uint_as_float(en.z), x * frcp(x + y + z), acc);
        }
        A[p*PAD + tid] = acc;
    }
    __syncthreads();

    // Phase C: coalesced store of the 128x64 output tile.
    float4* out4 = (float4*)(out + base);
    for (int i = tid; i < ROWS*PCOUNT/4; i += THREADS){
        int o = i*4, row = o >> 6, p = o & (PCOUNT-1);
        if (row < nrows){
            float4 v;
            v.x = A[(p  )*PAD + row];
            v.y = A[(p+1)*PAD + row];
            v.z = A[(p+2)*PAD + row];
            v.w = A[(p+3)*PAD + row];
            out4[i] = v;
        }
    }
}

extern "C" void kernel_launch(void* const* d_in, const int* in_sizes, int n_in,
                              void* d_out, int out_size)
{
    const float* ga  = (const float*)d_in[0];      // ground_atoms [B,64] f32
    const float* cw  = (const float*)d_in[1];      // clause_weights [C] f32
    const void*  lit = d_in[2];                    // literal_idx [C,3] i32-or-i64
    const int*   sgn = (const int*)d_in[3];        // sign_bits [C,3] i32
    float* out = (float*)d_out;

    int C = in_sizes[1];
    int B = in_sizes[0] / PCOUNT;
    int nblocks = (B + ROWS - 1) / ROWS;
    size_t smem = (size_t)(EROWS*PAD + PCOUNT*PAD) * sizeof(float)
                + NLIT * sizeof(uint4) + (PCOUNT + 2) * sizeof(int);  // ~105.5 KB

    cudaFuncSetAttribute(main_kernel, cudaFuncAttributeMaxDynamicSharedMemorySize, (int)smem);
    prep_kernel<<<1, THREADS>>>(cw, lit, sgn, C);
    main_kernel<<<nblocks, THREADS, smem>>>(ga, out, B);
}

// round 5
// speedup vs baseline: 2.5879x; 2.5879x over previous
#include <cuda_runtime.h>
#include <stdint.h>

#define THREADS 128
#define ROWS    32       // rows per block (small tile -> 4 blocks/SM)
#define PCOUNT  64       // predicates
#define PAD     33       // conflict-free row stride in shared (ROWS+1)
#define C_MAX   128
#define NSPLIT  4        // clause quarters, one per warp
#define EROWS   128      // E-table: exp(+g_p) at row p, exp(-g_p) at row p+64

__device__ uint4  g_pk[C_MAX];   // packed pre-multiplied indices (16-bit each)
__device__ float4 g_swl[C_MAX];  // sign*clamped_weight per literal

__device__ __forceinline__ float frcp(float x){ float y; asm("rcp.approx.f32 %0, %1;" : "=f"(y) : "f"(x)); return y; }
__device__ __forceinline__ float fex2(float x){ float y; asm("ex2.approx.f32 %0, %1;" : "=f"(y) : "f"(x)); return y; }

// literal_idx may physically be int32 (JAX x64-disabled) or int64; detect:
// int64 view of int32 data fuses two random indices -> out of [0,64) w.h.p.
__global__ void prep_kernel(const float* __restrict__ cw,
                            const void* __restrict__ litraw,
                            const int* __restrict__ sgn, int C)
{
    __shared__ int sh_is64;
    if (threadIdx.x == 0){
        const long long* v64 = (const long long*)litraw;
        int n = (C * 3) / 2;              // stays within int32-buffer bounds
        int ok = 1;
        for (int k = 0; k < n; k++){
            long long v = v64[k];
            if (v < 0 || v >= PCOUNT){ ok = 0; break; }
        }
        sh_is64 = ok;
    }
    __syncthreads();
    const int is64 = sh_is64;

    int c = blockIdx.x * blockDim.x + threadIdx.x;
    if (c >= C) return;
    float w = fminf(fmaxf(cw[c], 0.0f), 500.0f);     // clamp(0, 500)
    unsigned e[3], a[3]; float s[3];
    #pragma unroll
    for (int l = 0; l < 3; l++){
        int p = is64 ? (int)((const long long*)litraw)[c*3 + l]
                     :       ((const int*)litraw)[c*3 + l];
        int sb = sgn[c*3 + l];            // 1 -> +g half, 0 -> -g half
        e[l] = (unsigned)((p + (sb ? 0 : PCOUNT)) * PAD);
        a[l] = (unsigned)(p * PAD);
        s[l] = sb ? w : -w;
    }
    g_pk[c]  = make_uint4(e[0] | (e[1] << 16), e[2] | (a[0] << 16), a[1] | (a[2] << 16), 0u);
    g_swl[c] = make_float4(s[0], s[1], s[2], 0.0f);
}

__global__ void __launch_bounds__(THREADS)
main_kernel(const float* __restrict__ ga, float* __restrict__ out, int B)
{
    extern __shared__ float sh[];
    float* __restrict__ E = sh;                                // EROWS*PAD = 4224 f
    float* __restrict__ A = sh + EROWS*PAD;                    // NSPLIT * 64*33 = 8448 f
    uint4*  CI = (uint4*)(sh + EROWS*PAD + NSPLIT*PCOUNT*PAD);
    float4* CW = (float4*)(CI + C_MAX);

    const int tid  = threadIdx.x;
    const int lane = tid & 31;
    const int wrp  = tid >> 5;
    const long long rowbase = (long long)blockIdx.x * ROWS;
    long long rem = (long long)B - rowbase;
    const int nrows = rem < ROWS ? (int)rem : ROWS;
    const size_t base = (size_t)rowbase * PCOUNT;

    if (tid < C_MAX){ CI[tid] = g_pk[tid]; CW[tid] = g_swl[tid]; }

    // zero all 4 accumulator arrays (vectorized)
    float4* A4 = (float4*)A;
    #pragma unroll
    for (int i = tid; i < NSPLIT*PCOUNT*PAD/4; i += THREADS)
        A4[i] = make_float4(0.f, 0.f, 0.f, 0.f);

    // Phase A: coalesced 32x64 tile load; build exp table (exp(+g), rcp(exp)).
    const float4* ga4 = (const float4*)(ga + base);
    const float L2E = 1.4426950408889634f;
    #pragma unroll
    for (int i = tid; i < ROWS*PCOUNT/4; i += THREADS){
        int o = i * 4, row = o >> 6, p = o & (PCOUNT-1);
        if (row < nrows){
            float4 g = ga4[i];
            float t;
            t = fex2(g.x*L2E); E[(p  )*PAD+row] = t; E[(p+PCOUNT  )*PAD+row] = frcp(t);
            t = fex2(g.y*L2E); E[(p+1)*PAD+row] = t; E[(p+PCOUNT+1)*PAD+row] = frcp(t);
            t = fex2(g.z*L2E); E[(p+2)*PAD+row] = t; E[(p+PCOUNT+2)*PAD+row] = frcp(t);
            t = fex2(g.w*L2E); E[(p+3)*PAD+row] = t; E[(p+PCOUNT+3)*PAD+row] = frcp(t);
        }
    }
    __syncthreads();

    // Phase B: warp w owns clause quarter [32w, 32w+32) and private A_w.
    // Thread handles row `lane`. Static trip count (32) + unroll 8 gives 8
    // independent LDS/RMW chains in flight per thread; no cross-warp hazards.
    {
        float* __restrict__ Aw = A + wrp * (PCOUNT*PAD);
        const int c0 = wrp * (C_MAX/NSPLIT);
        #pragma unroll 8
        for (int c = c0; c < c0 + C_MAX/NSPLIT; c++){
            uint4 ci = CI[c]; float4 cw = CW[c];
            int e0 = (int)(ci.x & 0xFFFF), e1 = (int)(ci.x >> 16);
            int e2 = (int)(ci.y & 0xFFFF), a0 = (int)(ci.y >> 16);
            int a1 = (int)(ci.z & 0xFFFF), a2 = (int)(ci.z >> 16);
            float x0 = E[e0 + lane], x1 = E[e1 + lane], x2 = E[e2 + lane];
            float r  = frcp(x0 + x1 + x2);               // 1/sum(exp)
            Aw[a0 + lane] = fmaf(cw.x, x0*r, Aw[a0 + lane]);
            Aw[a1 + lane] = fmaf(cw.y, x1*r, Aw[a1 + lane]);
            Aw[a2 + lane] = fmaf(cw.z, x2*r, Aw[a2 + lane]);
        }
    }
    __syncthreads();

    // Reduce the 4 per-warp accumulators into A_0 (vectorized).
    {
        const int n4 = PCOUNT*PAD/4;   // 528
        for (int i = tid; i < n4; i += THREADS){
            float4 a = A4[i], b = A4[i + n4], c = A4[i + 2*n4], d = A4[i + 3*n4];
            a.x += b.x + c.x + d.x;
            a.y += b.y + c.y + d.y;
            a.z += b.z + c.z + d.z;
            a.w += b.w + c.w + d.w;
            A4[i] = a;
        }
    }
    __syncthreads();

    // Phase C: coalesced store of the 32x64 output tile.
    float4* out4 = (float4*)(out + base);
    #pragma unroll
    for (int i = tid; i < ROWS*PCOUNT/4; i += THREADS){
        int o = i*4, row = o >> 6, p = o & (PCOUNT-1);
        if (row < nrows){
            float4 v;
            v.x = A[(p  )*PAD + row];
            v.y = A[(p+1)*PAD + row];
            v.z = A[(p+2)*PAD + row];
            v.w = A[(p+3)*PAD + row];
            out4[i] = v;
        }
    }
}

extern "C" void kernel_launch(void* const* d_in, const int* in_sizes, int n_in,
                              void* d_out, int out_size)
{
    const float* ga  = (const float*)d_in[0];      // ground_atoms [B,64] f32
    const float* cw  = (const float*)d_in[1];      // clause_weights [C] f32
    const void*  lit = d_in[2];                    // literal_idx [C,3] i32-or-i64
    const int*   sgn = (const int*)d_in[3];        // sign_bits [C,3] i32
    float* out = (float*)d_out;

    int C = in_sizes[1];
    int B = in_sizes[0] / PCOUNT;
    int nblocks = (B + ROWS - 1) / ROWS;
    size_t smem = (size_t)(EROWS*PAD + NSPLIT*PCOUNT*PAD) * sizeof(float)
                + C_MAX * (sizeof(uint4) + sizeof(float4));   // ~54.7 KB -> 4 blocks/SM

    cudaFuncSetAttribute(main_kernel, cudaFuncAttributeMaxDynamicSharedMemorySize, (int)smem);
    prep_kernel<<<1, THREADS>>>(cw, lit, sgn, C);
    main_kernel<<<nblocks, THREADS, smem>>>(ga, out, B);
}